// round 7
// baseline (speedup 1.0000x reference)
#include <cuda_runtime.h>
#include <cuda_fp16.h>
#include <math.h>

#define B_DIM 4096
#define H_DIM 1024
#define K_DIM 2048

// GEMM tiling: C[4096 m][4096 n'] where n' = n*4 + gate (gate-interleaved)
// CTA: 128 threads = 4 warps (2m x 2n), warp tile 64m x 64n'
#define BM 128
#define BNP 128
#define BK 32                 // k per stage
#define KSTAGES (K_DIM / BK)  // 64
#define NBUF 4

// ---------------- device scratch (allocation-free rule: __device__ globals) ----
__device__ __align__(1024) __half g_Ah[(size_t)B_DIM * K_DIM];
__device__ __align__(1024) __half g_Bh[(size_t)4 * H_DIM * K_DIM];

// ---------------- helpers ----------------
__device__ __forceinline__ unsigned smem_u32(const void* p) {
    unsigned a;
    asm("{ .reg .u64 t; cvta.to.shared.u64 t, %1; cvt.u32.u64 %0, t; }" : "=r"(a) : "l"(p));
    return a;
}
__device__ __forceinline__ void cpa16(unsigned dst, const void* src) {
    asm volatile("cp.async.cg.shared.global [%0], [%1], 16;" :: "r"(dst), "l"(src) : "memory");
}
#define CPA_COMMIT() asm volatile("cp.async.commit_group;" ::: "memory")
#define CPA_WAIT2()  asm volatile("cp.async.wait_group 2;" ::: "memory")
#define CPA_WAIT0()  asm volatile("cp.async.wait_group 0;" ::: "memory")

__device__ __forceinline__ void ldsm4(unsigned &r0, unsigned &r1, unsigned &r2, unsigned &r3,
                                      unsigned addr) {
    asm volatile("ldmatrix.sync.aligned.m8n8.x4.shared.b16 {%0,%1,%2,%3}, [%4];"
                 : "=r"(r0), "=r"(r1), "=r"(r2), "=r"(r3) : "r"(addr));
}
__device__ __forceinline__ void mma16816(float* c, const unsigned* a, const unsigned* b) {
    asm volatile(
        "mma.sync.aligned.m16n8k16.row.col.f32.f16.f16.f32 "
        "{%0,%1,%2,%3}, {%4,%5,%6,%7}, {%8,%9}, {%0,%1,%2,%3};"
        : "+f"(c[0]), "+f"(c[1]), "+f"(c[2]), "+f"(c[3])
        : "r"(a[0]), "r"(a[1]), "r"(a[2]), "r"(a[3]), "r"(b[0]), "r"(b[1]));
}

// ---------------- merged conversion kernel ----------------
// blocks [0, 4096): A rows fp32->fp16;  [4096, 8192): W convert+transpose
__global__ __launch_bounds__(256) void conv_kernel(
    const float* __restrict__ x, const float* __restrict__ h_prev,
    const float* __restrict__ Wf, const float* __restrict__ Wi,
    const float* __restrict__ Wg, const float* __restrict__ Wo)
{
    __shared__ float s[32][65];
    int bid = blockIdx.x, t = threadIdx.x;
    if (bid < B_DIM) {
        int k = t * 8;
        const float* src = (k < H_DIM) ? (x + (size_t)bid * H_DIM + k)
                                       : (h_prev + (size_t)bid * H_DIM + (k - H_DIM));
        float4 v0 = *reinterpret_cast<const float4*>(src);
        float4 v1 = *reinterpret_cast<const float4*>(src + 4);
        float vs[8] = {v0.x, v0.y, v0.z, v0.w, v1.x, v1.y, v1.z, v1.w};
        __align__(16) __half hi[8];
        #pragma unroll
        for (int j = 0; j < 8; j++) hi[j] = __float2half_rn(vs[j]);
        *reinterpret_cast<uint4*>(g_Ah + (size_t)bid * K_DIM + k) = *reinterpret_cast<uint4*>(hi);
    } else {
        int w = bid - B_DIM;
        int k0 = (w & 63) * 32;
        int n0 = ((w >> 6) & 15) * 64;
        int g  = w >> 10;
        const float* W = (g == 0) ? Wf : (g == 1) ? Wi : (g == 2) ? Wg : Wo;
        #pragma unroll
        for (int i = 0; i < 8; i++) {
            int idx = t + i * 256;
            int kr = idx >> 6, nc = idx & 63;
            s[kr][nc] = W[(size_t)(k0 + kr) * H_DIM + n0 + nc];
        }
        __syncthreads();
        #pragma unroll
        for (int i = 0; i < 8; i++) {
            int idx = t + i * 256;
            int nn = idx >> 5, kk = idx & 31;
            g_Bh[(size_t)((n0 + nn) * 4 + g) * K_DIM + k0 + kk] = __float2half_rn(s[kk][nn]);
        }
    }
}

// ---------------- smem stage layout ----------------
// 2 tiles/stage, each 128 rows x 64B (BK=32 fp16). Swizzle: 16B chunk c at
// phys = c ^ ((row>>1)&3).
#define OFF_AH 0
#define OFF_BH (8 * 1024)
#define STAGE_BYTES (16 * 1024)
#define SMEM_TOTAL (NBUF * STAGE_BYTES)   // 64 KB -> 2 CTAs/SM

__device__ __forceinline__ void load_stage(unsigned base, int s, int m0, int np0, int t) {
    // 128 threads: thread t owns row t of both tiles (4 x 16B chunks each)
    unsigned rowoff = (unsigned)t * 64;
    unsigned sw = (unsigned)((t >> 1) & 3);
    const __half* pAh = g_Ah + (size_t)(m0 + t) * K_DIM + s * BK;
    const __half* pBh = g_Bh + (size_t)(np0 + t) * K_DIM + s * BK;
    #pragma unroll
    for (int j = 0; j < 4; j++) {
        unsigned phys = ((unsigned)j ^ sw) * 16;
        cpa16(base + OFF_AH + rowoff + phys, pAh + j * 8);
        cpa16(base + OFF_BH + rowoff + phys, pBh + j * 8);
    }
}

// ---------------- GEMM + fused LSTM epilogue ----------------
__global__ __launch_bounds__(128, 2) void lstm_gemm_kernel(
    const float* __restrict__ c_prev,
    const float* __restrict__ bfp, const float* __restrict__ bip,
    const float* __restrict__ bgp, const float* __restrict__ bop,
    float* __restrict__ h_out, float* __restrict__ c_out)
{
    extern __shared__ char smem[];
    unsigned sb = smem_u32(smem);
    const int t = threadIdx.x;
    const int w = t >> 5, lane = t & 31;
    const int m0  = blockIdx.y * BM;
    const int np0 = blockIdx.x * BNP;

    const int wm = (w >> 1) * 64;      // warp m base (0 or 64)
    const int wn = (w & 1) * 64;       // warp n' base (0 or 64)

    // A ldmatrix lane mapping (64B rows)
    const int lr = lane & 15;
    const int lc = lane >> 4;
    const unsigned swA = (unsigned)((lr >> 1) & 3);
    // B ldmatrix x4-pair lane mapping
    const int lb    = lane & 7;
    const int mid   = lane >> 3;
    const int niSel = mid >> 1;
    const int msub  = mid & 1;
    const unsigned swB = (unsigned)((lb >> 1) & 3);

    unsigned aRow[4], bRowP[4];
    #pragma unroll
    for (int mi = 0; mi < 4; mi++) aRow[mi] = (unsigned)(wm + mi * 16 + lr) * 64;
    #pragma unroll
    for (int p = 0; p < 4; p++) bRowP[p] = (unsigned)(wn + (p * 2 + niSel) * 8 + lb) * 64;

    // accumulators initialized with biases (col-mapped)
    const int tg = lane & 3;
    float acc[4][8][4];
    #pragma unroll
    for (int ni = 0; ni < 8; ni++) {
        int col0 = np0 + wn + ni * 8 + tg * 2;
        float b0, b1;
        {
            int g = col0 & 3, n = col0 >> 2;
            const float* p = (g == 0) ? bfp : (g == 1) ? bip : (g == 2) ? bgp : bop;
            b0 = p[n];
        }
        {
            int c1 = col0 + 1;
            int g = c1 & 3, n = c1 >> 2;
            const float* p = (g == 0) ? bfp : (g == 1) ? bip : (g == 2) ? bgp : bop;
            b1 = p[n];
        }
        #pragma unroll
        for (int mi = 0; mi < 4; mi++) {
            acc[mi][ni][0] = b0; acc[mi][ni][1] = b1;
            acc[mi][ni][2] = b0; acc[mi][ni][3] = b1;
        }
    }

    // prologue: 3 stages in flight
    #pragma unroll
    for (int p = 0; p < 3; p++) {
        load_stage(sb + (unsigned)p * STAGE_BYTES, p, m0, np0, t);
        CPA_COMMIT();
    }

    for (int s = 0; s < KSTAGES; s++) {
        if (s < KSTAGES - 2) CPA_WAIT2(); else CPA_WAIT0();
        __syncthreads();
        if (s + 3 < KSTAGES) {
            load_stage(sb + (unsigned)((s + 3) & 3) * STAGE_BYTES, s + 3, m0, np0, t);
            CPA_COMMIT();
        }
        unsigned base = sb + (unsigned)(s & 3) * STAGE_BYTES;

        #pragma unroll
        for (int k16 = 0; k16 < 2; k16++) {
            const unsigned cA = ((unsigned)(k16 * 2 + lc)   ^ swA) * 16;
            const unsigned cB = ((unsigned)(k16 * 2 + msub) ^ swB) * 16;

            unsigned bh[8][2];
            ldsm4(bh[0][0], bh[0][1], bh[1][0], bh[1][1], base + OFF_BH + bRowP[0] + cB);
            ldsm4(bh[2][0], bh[2][1], bh[3][0], bh[3][1], base + OFF_BH + bRowP[1] + cB);
            ldsm4(bh[4][0], bh[4][1], bh[5][0], bh[5][1], base + OFF_BH + bRowP[2] + cB);
            ldsm4(bh[6][0], bh[6][1], bh[7][0], bh[7][1], base + OFF_BH + bRowP[3] + cB);

            #pragma unroll
            for (int mi = 0; mi < 4; mi++) {
                unsigned ah[4];
                ldsm4(ah[0], ah[1], ah[2], ah[3], base + OFF_AH + aRow[mi] + cA);
                #pragma unroll
                for (int ni = 0; ni < 8; ni++)
                    mma16816(acc[mi][ni], ah, bh[ni]);
            }
        }
    }

    // ---- fused LSTM epilogue (biases already in acc) ----
    const int g8   = lane >> 2;
    const int odd  = tg & 1;
    const int nsel = tg >> 1;
    const int nwbase = blockIdx.x * 32 + (w & 1) * 16;

    #pragma unroll
    for (int mi = 0; mi < 4; mi++) {
        const int rbase = m0 + wm + mi * 16 + g8;
        const int row = rbase + (odd ? 8 : 0);
        #pragma unroll
        for (int ni = 0; ni < 8; ni++) {
            const int nout = nwbase + ni * 2 + nsel;
            float c0 = acc[mi][ni][0], c1 = acc[mi][ni][1];
            float c2 = acc[mi][ni][2], c3 = acc[mi][ni][3];
            float v0 = __shfl_xor_sync(0xffffffffu, c0, 1);
            float v1 = __shfl_xor_sync(0xffffffffu, c1, 1);
            float v2 = __shfl_xor_sync(0xffffffffu, c2, 1);
            float v3 = __shfl_xor_sync(0xffffffffu, c3, 1);
            float F = odd ? v2 : c0;
            float I = odd ? v3 : c1;
            float G = odd ? c2 : v0;
            float O = odd ? c3 : v1;

            size_t idx = (size_t)row * H_DIM + nout;
            float cp = c_prev[idx];
            float fg = 1.0f / (1.0f + expf(-F));
            float ig = 1.0f / (1.0f + expf(-I));
            float gg = tanhf(G);
            float og = 1.0f / (1.0f + expf(-O));
            float cn = fg * cp + ig * gg;
            c_out[idx] = cn;
            h_out[idx] = og * tanhf(cn);
        }
    }
}

// ---------------- launch ----------------
extern "C" void kernel_launch(void* const* d_in, const int* in_sizes, int n_in,
                              void* d_out, int out_size) {
    const float* x      = (const float*)d_in[0];
    const float* h_prev = (const float*)d_in[1];
    const float* c_prev = (const float*)d_in[2];
    const float* Wf     = (const float*)d_in[3];
    const float* bf     = (const float*)d_in[4];
    const float* Wi     = (const float*)d_in[5];
    const float* bi     = (const float*)d_in[6];
    const float* Wg     = (const float*)d_in[7];
    const float* bg     = (const float*)d_in[8];
    const float* Wo     = (const float*)d_in[9];
    const float* bo     = (const float*)d_in[10];

    float* out   = (float*)d_out;
    float* h_out = out;
    float* c_out = out + (size_t)B_DIM * H_DIM;

    cudaFuncSetAttribute(lstm_gemm_kernel,
                         cudaFuncAttributeMaxDynamicSharedMemorySize, SMEM_TOTAL);

    conv_kernel<<<2 * B_DIM, 256>>>(x, h_prev, Wf, Wi, Wg, Wo);
    lstm_gemm_kernel<<<dim3(4 * H_DIM / BNP, B_DIM / BM), 128, SMEM_TOTAL>>>(
        c_prev, bf, bi, bg, bo, h_out, c_out);
}

// round 8
// speedup vs baseline: 1.0035x; 1.0035x over previous
#include <cuda_runtime.h>
#include <cuda_fp16.h>
#include <math.h>

#define B_DIM 4096
#define H_DIM 1024
#define K_DIM 2048

// GEMM tiling: C[4096 m][4096 n'] where n' = n*4 + gate (gate-interleaved)
// CTA: 256 threads = 8 warps (2m x 4n), warp tile 64m x 32n'
#define BM 128
#define BNP 128
#define BK 64                 // k per stage
#define KSTAGES (K_DIM / BK)  // 32
#define NBUF 3

// ---------------- device scratch (allocation-free rule: __device__ globals) ----
__device__ __align__(1024) __half g_Ah[(size_t)B_DIM * K_DIM];
__device__ __align__(1024) __half g_Bh[(size_t)4 * H_DIM * K_DIM];

// ---------------- helpers ----------------
__device__ __forceinline__ unsigned smem_u32(const void* p) {
    unsigned a;
    asm("{ .reg .u64 t; cvta.to.shared.u64 t, %1; cvt.u32.u64 %0, t; }" : "=r"(a) : "l"(p));
    return a;
}
__device__ __forceinline__ void cpa16(unsigned dst, const void* src) {
    asm volatile("cp.async.cg.shared.global [%0], [%1], 16;" :: "r"(dst), "l"(src) : "memory");
}
#define CPA_COMMIT() asm volatile("cp.async.commit_group;" ::: "memory")
#define CPA_WAIT1()  asm volatile("cp.async.wait_group 1;" ::: "memory")
#define CPA_WAIT0()  asm volatile("cp.async.wait_group 0;" ::: "memory")

__device__ __forceinline__ void ldsm4(unsigned &r0, unsigned &r1, unsigned &r2, unsigned &r3,
                                      unsigned addr) {
    asm volatile("ldmatrix.sync.aligned.m8n8.x4.shared.b16 {%0,%1,%2,%3}, [%4];"
                 : "=r"(r0), "=r"(r1), "=r"(r2), "=r"(r3) : "r"(addr));
}
__device__ __forceinline__ void mma16816(float* c, const unsigned* a, const unsigned* b) {
    asm volatile(
        "mma.sync.aligned.m16n8k16.row.col.f32.f16.f16.f32 "
        "{%0,%1,%2,%3}, {%4,%5,%6,%7}, {%8,%9}, {%0,%1,%2,%3};"
        : "+f"(c[0]), "+f"(c[1]), "+f"(c[2]), "+f"(c[3])
        : "r"(a[0]), "r"(a[1]), "r"(a[2]), "r"(a[3]), "r"(b[0]), "r"(b[1]));
}

__device__ __forceinline__ float fsigmoid(float x) {
    return 1.0f / (1.0f + __expf(-x));
}
__device__ __forceinline__ float ftanh(float x) {
    return 2.0f / (1.0f + __expf(-2.0f * x)) - 1.0f;
}

// ---------------- merged conversion kernel ----------------
// blocks [0, 4096): A rows fp32->fp16;  [4096, 8192): W convert+transpose
__global__ __launch_bounds__(256) void conv_kernel(
    const float* __restrict__ x, const float* __restrict__ h_prev,
    const float* __restrict__ Wf, const float* __restrict__ Wi,
    const float* __restrict__ Wg, const float* __restrict__ Wo)
{
    __shared__ float s[32][65];
    int bid = blockIdx.x, t = threadIdx.x;
    if (bid < B_DIM) {
        int k = t * 8;
        const float* src = (k < H_DIM) ? (x + (size_t)bid * H_DIM + k)
                                       : (h_prev + (size_t)bid * H_DIM + (k - H_DIM));
        float4 v0 = *reinterpret_cast<const float4*>(src);
        float4 v1 = *reinterpret_cast<const float4*>(src + 4);
        float vs[8] = {v0.x, v0.y, v0.z, v0.w, v1.x, v1.y, v1.z, v1.w};
        __align__(16) __half hi[8];
        #pragma unroll
        for (int j = 0; j < 8; j++) hi[j] = __float2half_rn(vs[j]);
        *reinterpret_cast<uint4*>(g_Ah + (size_t)bid * K_DIM + k) = *reinterpret_cast<uint4*>(hi);
    } else {
        int w = bid - B_DIM;
        int k0 = (w & 63) * 32;
        int n0 = ((w >> 6) & 15) * 64;
        int g  = w >> 10;
        const float* W = (g == 0) ? Wf : (g == 1) ? Wi : (g == 2) ? Wg : Wo;
        #pragma unroll
        for (int i = 0; i < 8; i++) {
            int idx = t + i * 256;
            int kr = idx >> 6, nc = idx & 63;
            s[kr][nc] = W[(size_t)(k0 + kr) * H_DIM + n0 + nc];
        }
        __syncthreads();
        #pragma unroll
        for (int i = 0; i < 8; i++) {
            int idx = t + i * 256;
            int nn = idx >> 5, kk = idx & 31;
            g_Bh[(size_t)((n0 + nn) * 4 + g) * K_DIM + k0 + kk] = __float2half_rn(s[kk][nn]);
        }
    }
}

// ---------------- smem stage layout ----------------
// 2 tiles/stage, each 128 rows x 128B (BK=64 fp16). Swizzle: 16B chunk c at
// phys = c ^ (row & 7).
#define OFF_AH 0
#define OFF_BH (16 * 1024)
#define STAGE_BYTES (32 * 1024)
#define SMEM_TOTAL (NBUF * STAGE_BYTES)   // 96 KB -> 2 CTAs/SM

__device__ __forceinline__ void load_stage(unsigned base, int s, int m0, int np0, int t) {
    int r = t >> 1;
    int c0 = (t & 1) * 4;
    unsigned rowoff = (unsigned)r * 128;
    unsigned sw = (unsigned)(r & 7);
    const __half* pAh = g_Ah + (size_t)(m0 + r) * K_DIM + s * BK + c0 * 8;
    const __half* pBh = g_Bh + (size_t)(np0 + r) * K_DIM + s * BK + c0 * 8;
    #pragma unroll
    for (int j = 0; j < 4; j++) {
        unsigned phys = ((unsigned)(c0 + j) ^ sw) * 16;
        cpa16(base + OFF_AH + rowoff + phys, pAh + j * 8);
        cpa16(base + OFF_BH + rowoff + phys, pBh + j * 8);
    }
}

// ---------------- GEMM + fused LSTM epilogue ----------------
__global__ __launch_bounds__(256, 2) void lstm_gemm_kernel(
    const float* __restrict__ c_prev,
    const float* __restrict__ bfp, const float* __restrict__ bip,
    const float* __restrict__ bgp, const float* __restrict__ bop,
    float* __restrict__ h_out, float* __restrict__ c_out)
{
    extern __shared__ char smem[];
    unsigned sb = smem_u32(smem);
    const int t = threadIdx.x;
    const int w = t >> 5, lane = t & 31;
    const int m0  = blockIdx.y * BM;
    const int np0 = blockIdx.x * BNP;

    const int wm = (w >> 2) * 64;
    const int wn = (w & 3) * 32;

    // A ldmatrix lane mapping (128B rows)
    const int lr = lane & 15;
    const int lc = lane >> 4;
    const unsigned swA = (unsigned)(lr & 7);
    // B ldmatrix x4-pair lane mapping
    const int lb    = lane & 7;
    const int mid   = lane >> 3;
    const int niSel = mid >> 1;
    const int msub  = mid & 1;
    const unsigned swB = (unsigned)lb;

    unsigned aRow[4], bRowP[2];
    #pragma unroll
    for (int mi = 0; mi < 4; mi++) aRow[mi] = (unsigned)(wm + mi * 16 + lr) * 128;
    #pragma unroll
    for (int p = 0; p < 2; p++) bRowP[p] = (unsigned)(wn + (p * 2 + niSel) * 8 + lb) * 128;

    // accumulators initialized with biases (col-mapped)
    const int tg = lane & 3;
    float acc[4][4][4];
    #pragma unroll
    for (int ni = 0; ni < 4; ni++) {
        int col0 = np0 + wn + ni * 8 + tg * 2;
        float b0, b1;
        {
            int g = col0 & 3, n = col0 >> 2;
            const float* p = (g == 0) ? bfp : (g == 1) ? bip : (g == 2) ? bgp : bop;
            b0 = p[n];
        }
        {
            int c1 = col0 + 1;
            int g = c1 & 3, n = c1 >> 2;
            const float* p = (g == 0) ? bfp : (g == 1) ? bip : (g == 2) ? bgp : bop;
            b1 = p[n];
        }
        #pragma unroll
        for (int mi = 0; mi < 4; mi++) {
            acc[mi][ni][0] = b0; acc[mi][ni][1] = b1;
            acc[mi][ni][2] = b0; acc[mi][ni][3] = b1;
        }
    }

    // prologue: 2 stages in flight
    load_stage(sb + 0 * STAGE_BYTES, 0, m0, np0, t); CPA_COMMIT();
    load_stage(sb + 1 * STAGE_BYTES, 1, m0, np0, t); CPA_COMMIT();

    unsigned bufIdx = 0;
    for (int s = 0; s < KSTAGES; s++) {
        if (s + 1 < KSTAGES) CPA_WAIT1(); else CPA_WAIT0();
        __syncthreads();
        unsigned base = sb + bufIdx * STAGE_BYTES;
        unsigned pb = bufIdx + 2; if (pb >= NBUF) pb -= NBUF;
        if (++bufIdx == NBUF) bufIdx = 0;

        #pragma unroll
        for (int k16 = 0; k16 < 4; k16++) {
            const unsigned cA = ((unsigned)(k16 * 2 + lc)   ^ swA) * 16;
            const unsigned cB = ((unsigned)(k16 * 2 + msub) ^ swB) * 16;

            unsigned bh[4][2];
            ldsm4(bh[0][0], bh[0][1], bh[1][0], bh[1][1], base + OFF_BH + bRowP[0] + cB);
            ldsm4(bh[2][0], bh[2][1], bh[3][0], bh[3][1], base + OFF_BH + bRowP[1] + cB);

            #pragma unroll
            for (int mi = 0; mi < 4; mi++) {
                unsigned ah[4];
                ldsm4(ah[0], ah[1], ah[2], ah[3], base + OFF_AH + aRow[mi] + cA);
                #pragma unroll
                for (int ni = 0; ni < 4; ni++)
                    mma16816(acc[mi][ni], ah, bh[ni]);
            }

            // issue the next-stage prefetch after the first k16 block so the
            // cp.async burst doesn't delay the critical ldsm's at stage start
            if (k16 == 0 && s + 2 < KSTAGES) {
                load_stage(sb + pb * STAGE_BYTES, s + 2, m0, np0, t);
                CPA_COMMIT();
            }
        }
    }

    // ---- fused LSTM epilogue (biases already in acc) ----
    const int g8   = lane >> 2;
    const int odd  = tg & 1;
    const int nsel = tg >> 1;
    const int nwbase = blockIdx.x * 32 + (w & 3) * 8;

    #pragma unroll
    for (int mi = 0; mi < 4; mi++) {
        const int rbase = m0 + wm + mi * 16 + g8;
        const int row = rbase + (odd ? 8 : 0);
        #pragma unroll
        for (int ni = 0; ni < 4; ni++) {
            const int nout = nwbase + ni * 2 + nsel;
            float c0 = acc[mi][ni][0], c1 = acc[mi][ni][1];
            float c2 = acc[mi][ni][2], c3 = acc[mi][ni][3];
            float v0 = __shfl_xor_sync(0xffffffffu, c0, 1);
            float v1 = __shfl_xor_sync(0xffffffffu, c1, 1);
            float v2 = __shfl_xor_sync(0xffffffffu, c2, 1);
            float v3 = __shfl_xor_sync(0xffffffffu, c3, 1);
            float F = odd ? v2 : c0;
            float I = odd ? v3 : c1;
            float G = odd ? c2 : v0;
            float O = odd ? c3 : v1;

            size_t idx = (size_t)row * H_DIM + nout;
            float cp = c_prev[idx];
            float fg = fsigmoid(F);
            float ig = fsigmoid(I);
            float gg = ftanh(G);
            float og = fsigmoid(O);
            float cn = fg * cp + ig * gg;
            c_out[idx] = cn;
            h_out[idx] = og * ftanh(cn);
        }
    }
}

// ---------------- launch ----------------
extern "C" void kernel_launch(void* const* d_in, const int* in_sizes, int n_in,
                              void* d_out, int out_size) {
    const float* x      = (const float*)d_in[0];
    const float* h_prev = (const float*)d_in[1];
    const float* c_prev = (const float*)d_in[2];
    const float* Wf     = (const float*)d_in[3];
    const float* bf     = (const float*)d_in[4];
    const float* Wi     = (const float*)d_in[5];
    const float* bi     = (const float*)d_in[6];
    const float* Wg     = (const float*)d_in[7];
    const float* bg     = (const float*)d_in[8];
    const float* Wo     = (const float*)d_in[9];
    const float* bo     = (const float*)d_in[10];

    float* out   = (float*)d_out;
    float* h_out = out;
    float* c_out = out + (size_t)B_DIM * H_DIM;

    cudaFuncSetAttribute(lstm_gemm_kernel,
                         cudaFuncAttributeMaxDynamicSharedMemorySize, SMEM_TOTAL);

    conv_kernel<<<2 * B_DIM, 256>>>(x, h_prev, Wf, Wi, Wg, Wo);
    lstm_gemm_kernel<<<dim3(4 * H_DIM / BNP, B_DIM / BM), 256, SMEM_TOTAL>>>(
        c_prev, bf, bi, bg, bo, h_out, c_out);
}

// round 9
// speedup vs baseline: 1.4895x; 1.4842x over previous
#include <cuda_runtime.h>
#include <cuda_fp16.h>
#include <math.h>

#define B_DIM 4096
#define H_DIM 1024
#define K_DIM 2048

// GEMM tiling: C[4096 m][4096 n'] where n' = n*4 + gate (gate-interleaved)
// CTA: 256 threads = 8 warps (2m x 4n), warp tile 64m x 32n'  [round-6 proven config]
#define BM 128
#define BNP 128
#define BK 32                 // k per stage
#define KSTAGES (K_DIM / BK)  // 64
#define NBUF 6

// ---------------- device scratch (allocation-free rule: __device__ globals) ----
__device__ __align__(1024) __half g_Ah[(size_t)B_DIM * K_DIM];
__device__ __align__(1024) __half g_Bh[(size_t)4 * H_DIM * K_DIM];

// ---------------- helpers ----------------
__device__ __forceinline__ unsigned smem_u32(const void* p) {
    unsigned a;
    asm("{ .reg .u64 t; cvta.to.shared.u64 t, %1; cvt.u32.u64 %0, t; }" : "=r"(a) : "l"(p));
    return a;
}
__device__ __forceinline__ void cpa16(unsigned dst, const void* src) {
    asm volatile("cp.async.cg.shared.global [%0], [%1], 16;" :: "r"(dst), "l"(src) : "memory");
}
#define CPA_COMMIT() asm volatile("cp.async.commit_group;" ::: "memory")
#define CPA_WAIT4()  asm volatile("cp.async.wait_group 4;" ::: "memory")
#define CPA_WAIT0()  asm volatile("cp.async.wait_group 0;" ::: "memory")

__device__ __forceinline__ void ldsm4(unsigned &r0, unsigned &r1, unsigned &r2, unsigned &r3,
                                      unsigned addr) {
    asm volatile("ldmatrix.sync.aligned.m8n8.x4.shared.b16 {%0,%1,%2,%3}, [%4];"
                 : "=r"(r0), "=r"(r1), "=r"(r2), "=r"(r3) : "r"(addr));
}
__device__ __forceinline__ void mma16816(float* c, const unsigned* a, const unsigned* b) {
    asm volatile(
        "mma.sync.aligned.m16n8k16.row.col.f32.f16.f16.f32 "
        "{%0,%1,%2,%3}, {%4,%5,%6,%7}, {%8,%9}, {%0,%1,%2,%3};"
        : "+f"(c[0]), "+f"(c[1]), "+f"(c[2]), "+f"(c[3])
        : "r"(a[0]), "r"(a[1]), "r"(a[2]), "r"(a[3]), "r"(b[0]), "r"(b[1]));
}

__device__ __forceinline__ float fsigmoid(float x) {
    return 1.0f / (1.0f + __expf(-x));
}
__device__ __forceinline__ float ftanh(float x) {
    return 2.0f / (1.0f + __expf(-2.0f * x)) - 1.0f;
}

// ---------------- merged conversion kernel ----------------
// blocks [0, 4096): A rows fp32->fp16
// blocks [4096, 6144): W convert+transpose, 64k x 64n tiles, vectorized
__global__ __launch_bounds__(256) void conv_kernel(
    const float* __restrict__ x, const float* __restrict__ h_prev,
    const float* __restrict__ Wf, const float* __restrict__ Wi,
    const float* __restrict__ Wg, const float* __restrict__ Wo)
{
    __shared__ float s[64][65];
    int bid = blockIdx.x, t = threadIdx.x;
    if (bid < B_DIM) {
        int k = t * 8;
        const float* src = (k < H_DIM) ? (x + (size_t)bid * H_DIM + k)
                                       : (h_prev + (size_t)bid * H_DIM + (k - H_DIM));
        float4 v0 = *reinterpret_cast<const float4*>(src);
        float4 v1 = *reinterpret_cast<const float4*>(src + 4);
        float vs[8] = {v0.x, v0.y, v0.z, v0.w, v1.x, v1.y, v1.z, v1.w};
        __align__(16) __half hi[8];
        #pragma unroll
        for (int j = 0; j < 8; j++) hi[j] = __float2half_rn(vs[j]);
        *reinterpret_cast<uint4*>(g_Ah + (size_t)bid * K_DIM + k) = *reinterpret_cast<uint4*>(hi);
    } else {
        // W tile: 64 k-rows x 64 n-cols, one gate
        int w = bid - B_DIM;
        int k0 = (w & 31) * 64;           // 2048/64 = 32
        int n0 = ((w >> 5) & 15) * 64;    // 1024/64 = 16
        int g  = w >> 9;                  // 4 gates
        const float* W = (g == 0) ? Wf : (g == 1) ? Wi : (g == 2) ? Wg : Wo;
        // load 64x64 floats via float4 (coalesced)
        #pragma unroll
        for (int i = 0; i < 4; i++) {
            int idx4 = t + i * 256;           // 0..1023
            int kr = idx4 >> 4;               // 16 float4 per 64-float row
            int c4 = idx4 & 15;
            float4 v = *reinterpret_cast<const float4*>(
                &W[(size_t)(k0 + kr) * H_DIM + n0 + c4 * 4]);
            s[kr][c4 * 4 + 0] = v.x;
            s[kr][c4 * 4 + 1] = v.y;
            s[kr][c4 * 4 + 2] = v.z;
            s[kr][c4 * 4 + 3] = v.w;
        }
        __syncthreads();
        // write transposed rows (n*4+g) as __half2 (coalesced 4B stores)
        #pragma unroll
        for (int i = 0; i < 8; i++) {
            int idx2 = t + i * 256;           // 0..2047 = 64 n x 32 k-pairs
            int nn = idx2 >> 5;
            int kp = idx2 & 31;
            __half2 hv = __floats2half2_rn(s[kp * 2][nn], s[kp * 2 + 1][nn]);
            *reinterpret_cast<__half2*>(
                &g_Bh[(size_t)((n0 + nn) * 4 + g) * K_DIM + k0 + kp * 2]) = hv;
        }
    }
}

// ---------------- smem stage layout ----------------
// 2 tiles/stage, each 128 rows x 64B (BK=32 fp16). Swizzle: 16B chunk c at
// phys = c ^ ((row>>1)&3).
#define OFF_AH 0
#define OFF_BH (8 * 1024)
#define STAGE_BYTES (16 * 1024)
#define SMEM_TOTAL (NBUF * STAGE_BYTES)   // 96 KB -> 2 CTAs/SM

__device__ __forceinline__ void load_stage(unsigned base, int s, int m0, int np0, int t) {
    int r = t >> 1;
    int cpair = (t & 1) * 2;
    unsigned rowoff = (unsigned)r * 64;
    unsigned sw = (unsigned)((r >> 1) & 3);
    const __half* pAh = g_Ah + (size_t)(m0 + r) * K_DIM + s * BK + cpair * 8;
    const __half* pBh = g_Bh + (size_t)(np0 + r) * K_DIM + s * BK + cpair * 8;
    #pragma unroll
    for (int j = 0; j < 2; j++) {
        unsigned phys = ((unsigned)(cpair + j) ^ sw) * 16;
        cpa16(base + OFF_AH + rowoff + phys, pAh + j * 8);
        cpa16(base + OFF_BH + rowoff + phys, pBh + j * 8);
    }
}

// ---------------- GEMM + fused LSTM epilogue ----------------
__global__ __launch_bounds__(256, 2) void lstm_gemm_kernel(
    const float* __restrict__ c_prev,
    const float* __restrict__ bfp, const float* __restrict__ bip,
    const float* __restrict__ bgp, const float* __restrict__ bop,
    float* __restrict__ h_out, float* __restrict__ c_out)
{
    extern __shared__ char smem[];
    unsigned sb = smem_u32(smem);
    const int t = threadIdx.x;
    const int w = t >> 5, lane = t & 31;
    const int m0  = blockIdx.y * BM;
    const int np0 = blockIdx.x * BNP;

    const int wm = (w >> 2) * 64;
    const int wn = (w & 3) * 32;

    // A ldmatrix lane mapping (64B rows)
    const int lr = lane & 15;
    const int lc = lane >> 4;
    const unsigned swA = (unsigned)((lr >> 1) & 3);
    // B ldmatrix x4-pair lane mapping
    const int lb    = lane & 7;
    const int mid   = lane >> 3;
    const int niSel = mid >> 1;
    const int msub  = mid & 1;
    const unsigned swB = (unsigned)((lb >> 1) & 3);

    unsigned aRow[4], bRowP[2];
    #pragma unroll
    for (int mi = 0; mi < 4; mi++) aRow[mi] = (unsigned)(wm + mi * 16 + lr) * 64;
    #pragma unroll
    for (int p = 0; p < 2; p++) bRowP[p] = (unsigned)(wn + (p * 2 + niSel) * 8 + lb) * 64;

    // accumulators initialized with biases (col-mapped)
    const int tg = lane & 3;
    float acc[4][4][4];
    #pragma unroll
    for (int ni = 0; ni < 4; ni++) {
        int col0 = np0 + wn + ni * 8 + tg * 2;
        float b0, b1;
        {
            int g = col0 & 3, n = col0 >> 2;
            const float* p = (g == 0) ? bfp : (g == 1) ? bip : (g == 2) ? bgp : bop;
            b0 = p[n];
        }
        {
            int c1 = col0 + 1;
            int g = c1 & 3, n = c1 >> 2;
            const float* p = (g == 0) ? bfp : (g == 1) ? bip : (g == 2) ? bgp : bop;
            b1 = p[n];
        }
        #pragma unroll
        for (int mi = 0; mi < 4; mi++) {
            acc[mi][ni][0] = b0; acc[mi][ni][1] = b1;
            acc[mi][ni][2] = b0; acc[mi][ni][3] = b1;
        }
    }

    // prologue: 5 stages in flight
    #pragma unroll
    for (int p = 0; p < 5; p++) {
        load_stage(sb + (unsigned)p * STAGE_BYTES, p, m0, np0, t);
        CPA_COMMIT();
    }

    unsigned bufIdx = 0;
    for (int s = 0; s < KSTAGES; s++) {
        if (s < KSTAGES - 4) CPA_WAIT4(); else CPA_WAIT0();
        __syncthreads();
        if (s + 5 < KSTAGES) {
            unsigned pb = bufIdx + 5; if (pb >= NBUF) pb -= NBUF;
            load_stage(sb + pb * STAGE_BYTES, s + 5, m0, np0, t);
            CPA_COMMIT();
        }
        unsigned base = sb + bufIdx * STAGE_BYTES;
        if (++bufIdx == NBUF) bufIdx = 0;

        #pragma unroll
        for (int k16 = 0; k16 < 2; k16++) {
            const unsigned cA = ((unsigned)(k16 * 2 + lc)   ^ swA) * 16;
            const unsigned cB = ((unsigned)(k16 * 2 + msub) ^ swB) * 16;

            unsigned bh[4][2];
            ldsm4(bh[0][0], bh[0][1], bh[1][0], bh[1][1], base + OFF_BH + bRowP[0] + cB);
            ldsm4(bh[2][0], bh[2][1], bh[3][0], bh[3][1], base + OFF_BH + bRowP[1] + cB);

            #pragma unroll
            for (int mi = 0; mi < 4; mi++) {
                unsigned ah[4];
                ldsm4(ah[0], ah[1], ah[2], ah[3], base + OFF_AH + aRow[mi] + cA);
                #pragma unroll
                for (int ni = 0; ni < 4; ni++)
                    mma16816(acc[mi][ni], ah, bh[ni]);
            }
        }
    }

    // ---- fused LSTM epilogue (biases already in acc, fast-math MUFU) ----
    const int g8   = lane >> 2;
    const int odd  = tg & 1;
    const int nsel = tg >> 1;
    const int nwbase = blockIdx.x * 32 + (w & 3) * 8;

    #pragma unroll
    for (int mi = 0; mi < 4; mi++) {
        const int rbase = m0 + wm + mi * 16 + g8;
        const int row = rbase + (odd ? 8 : 0);
        #pragma unroll
        for (int ni = 0; ni < 4; ni++) {
            const int nout = nwbase + ni * 2 + nsel;
            float c0 = acc[mi][ni][0], c1 = acc[mi][ni][1];
            float c2 = acc[mi][ni][2], c3 = acc[mi][ni][3];
            float v0 = __shfl_xor_sync(0xffffffffu, c0, 1);
            float v1 = __shfl_xor_sync(0xffffffffu, c1, 1);
            float v2 = __shfl_xor_sync(0xffffffffu, c2, 1);
            float v3 = __shfl_xor_sync(0xffffffffu, c3, 1);
            float F = odd ? v2 : c0;
            float I = odd ? v3 : c1;
            float G = odd ? c2 : v0;
            float O = odd ? c3 : v1;

            size_t idx = (size_t)row * H_DIM + nout;
            float cp = c_prev[idx];
            float fg = fsigmoid(F);
            float ig = fsigmoid(I);
            float gg = ftanh(G);
            float og = fsigmoid(O);
            float cn = fg * cp + ig * gg;
            c_out[idx] = cn;
            h_out[idx] = og * ftanh(cn);
        }
    }
}

// ---------------- launch ----------------
extern "C" void kernel_launch(void* const* d_in, const int* in_sizes, int n_in,
                              void* d_out, int out_size) {
    const float* x      = (const float*)d_in[0];
    const float* h_prev = (const float*)d_in[1];
    const float* c_prev = (const float*)d_in[2];
    const float* Wf     = (const float*)d_in[3];
    const float* bf     = (const float*)d_in[4];
    const float* Wi     = (const float*)d_in[5];
    const float* bi     = (const float*)d_in[6];
    const float* Wg     = (const float*)d_in[7];
    const float* bg     = (const float*)d_in[8];
    const float* Wo     = (const float*)d_in[9];
    const float* bo     = (const float*)d_in[10];

    float* out   = (float*)d_out;
    float* h_out = out;
    float* c_out = out + (size_t)B_DIM * H_DIM;

    cudaFuncSetAttribute(lstm_gemm_kernel,
                         cudaFuncAttributeMaxDynamicSharedMemorySize, SMEM_TOTAL);

    conv_kernel<<<B_DIM + 2048, 256>>>(x, h_prev, Wf, Wi, Wg, Wo);
    lstm_gemm_kernel<<<dim3(4 * H_DIM / BNP, B_DIM / BM), 256, SMEM_TOTAL>>>(
        c_prev, bf, bi, bg, bo, h_out, c_out);
}

// round 11
// speedup vs baseline: 1.4997x; 1.0069x over previous
#include <cuda_runtime.h>
#include <cuda_fp16.h>
#include <math.h>

#define B_DIM 4096
#define H_DIM 1024
#define K_DIM 2048

// GEMM tiling: C[4096 m][4096 n'] where n' = n*4 + gate (gate-interleaved)
// CTA: 256 threads = 8 warps (2m x 4n), warp tile 64m x 32n'
// Pair-stage barriers: barrier every 2 stages; NBUF=7 so the two per-pair
// prefetches land in genuinely free slots (round-10 raced with NBUF=6).
#define BM 128
#define BNP 128
#define BK 32                 // k per stage
#define KSTAGES (K_DIM / BK)  // 64
#define PAIRS (KSTAGES / 2)   // 32
#define NBUF 7

// ---------------- device scratch (allocation-free rule: __device__ globals) ----
__device__ __align__(1024) __half g_Ah[(size_t)B_DIM * K_DIM];
__device__ __align__(1024) __half g_Bh[(size_t)4 * H_DIM * K_DIM];

// ---------------- helpers ----------------
__device__ __forceinline__ unsigned smem_u32(const void* p) {
    unsigned a;
    asm("{ .reg .u64 t; cvta.to.shared.u64 t, %1; cvt.u32.u64 %0, t; }" : "=r"(a) : "l"(p));
    return a;
}
__device__ __forceinline__ void cpa16(unsigned dst, const void* src) {
    asm volatile("cp.async.cg.shared.global [%0], [%1], 16;" :: "r"(dst), "l"(src) : "memory");
}
#define CPA_COMMIT() asm volatile("cp.async.commit_group;" ::: "memory")
#define CPA_WAIT3()  asm volatile("cp.async.wait_group 3;" ::: "memory")
#define CPA_WAIT0()  asm volatile("cp.async.wait_group 0;" ::: "memory")

__device__ __forceinline__ void ldsm4(unsigned &r0, unsigned &r1, unsigned &r2, unsigned &r3,
                                      unsigned addr) {
    asm volatile("ldmatrix.sync.aligned.m8n8.x4.shared.b16 {%0,%1,%2,%3}, [%4];"
                 : "=r"(r0), "=r"(r1), "=r"(r2), "=r"(r3) : "r"(addr));
}
__device__ __forceinline__ void mma16816(float* c, const unsigned* a, const unsigned* b) {
    asm volatile(
        "mma.sync.aligned.m16n8k16.row.col.f32.f16.f16.f32 "
        "{%0,%1,%2,%3}, {%4,%5,%6,%7}, {%8,%9}, {%0,%1,%2,%3};"
        : "+f"(c[0]), "+f"(c[1]), "+f"(c[2]), "+f"(c[3])
        : "r"(a[0]), "r"(a[1]), "r"(a[2]), "r"(a[3]), "r"(b[0]), "r"(b[1]));
}

__device__ __forceinline__ float fsigmoid(float x) {
    return 1.0f / (1.0f + __expf(-x));
}
__device__ __forceinline__ float ftanh(float x) {
    return 2.0f / (1.0f + __expf(-2.0f * x)) - 1.0f;
}

// ---------------- merged conversion kernel ----------------
// blocks [0, 4096): A rows fp32->fp16
// blocks [4096, 6144): W convert+transpose, 64k x 64n tiles, vectorized
__global__ __launch_bounds__(256) void conv_kernel(
    const float* __restrict__ x, const float* __restrict__ h_prev,
    const float* __restrict__ Wf, const float* __restrict__ Wi,
    const float* __restrict__ Wg, const float* __restrict__ Wo)
{
    __shared__ float s[64][65];
    int bid = blockIdx.x, t = threadIdx.x;
    if (bid < B_DIM) {
        int k = t * 8;
        const float* src = (k < H_DIM) ? (x + (size_t)bid * H_DIM + k)
                                       : (h_prev + (size_t)bid * H_DIM + (k - H_DIM));
        float4 v0 = *reinterpret_cast<const float4*>(src);
        float4 v1 = *reinterpret_cast<const float4*>(src + 4);
        float vs[8] = {v0.x, v0.y, v0.z, v0.w, v1.x, v1.y, v1.z, v1.w};
        __align__(16) __half hi[8];
        #pragma unroll
        for (int j = 0; j < 8; j++) hi[j] = __float2half_rn(vs[j]);
        *reinterpret_cast<uint4*>(g_Ah + (size_t)bid * K_DIM + k) = *reinterpret_cast<uint4*>(hi);
    } else {
        int w = bid - B_DIM;
        int k0 = (w & 31) * 64;
        int n0 = ((w >> 5) & 15) * 64;
        int g  = w >> 9;
        const float* W = (g == 0) ? Wf : (g == 1) ? Wi : (g == 2) ? Wg : Wo;
        #pragma unroll
        for (int i = 0; i < 4; i++) {
            int idx4 = t + i * 256;
            int kr = idx4 >> 4;
            int c4 = idx4 & 15;
            float4 v = *reinterpret_cast<const float4*>(
                &W[(size_t)(k0 + kr) * H_DIM + n0 + c4 * 4]);
            s[kr][c4 * 4 + 0] = v.x;
            s[kr][c4 * 4 + 1] = v.y;
            s[kr][c4 * 4 + 2] = v.z;
            s[kr][c4 * 4 + 3] = v.w;
        }
        __syncthreads();
        #pragma unroll
        for (int i = 0; i < 8; i++) {
            int idx2 = t + i * 256;
            int nn = idx2 >> 5;
            int kp = idx2 & 31;
            __half2 hv = __floats2half2_rn(s[kp * 2][nn], s[kp * 2 + 1][nn]);
            *reinterpret_cast<__half2*>(
                &g_Bh[(size_t)((n0 + nn) * 4 + g) * K_DIM + k0 + kp * 2]) = hv;
        }
    }
}

// ---------------- smem stage layout ----------------
// 2 tiles/stage, each 128 rows x 64B (BK=32 fp16). Swizzle: 16B chunk c at
// phys = c ^ ((row>>1)&3).
#define OFF_AH 0
#define OFF_BH (8 * 1024)
#define STAGE_BYTES (16 * 1024)
#define SMEM_TOTAL (NBUF * STAGE_BYTES)   // 112 KB -> 2 CTAs/SM (224 of 228 KB)

__device__ __forceinline__ void load_stage(unsigned base, int s, int m0, int np0, int t) {
    int r = t >> 1;
    int cpair = (t & 1) * 2;
    unsigned rowoff = (unsigned)r * 64;
    unsigned sw = (unsigned)((r >> 1) & 3);
    const __half* pAh = g_Ah + (size_t)(m0 + r) * K_DIM + s * BK + cpair * 8;
    const __half* pBh = g_Bh + (size_t)(np0 + r) * K_DIM + s * BK + cpair * 8;
    #pragma unroll
    for (int j = 0; j < 2; j++) {
        unsigned phys = ((unsigned)(cpair + j) ^ sw) * 16;
        cpa16(base + OFF_AH + rowoff + phys, pAh + j * 8);
        cpa16(base + OFF_BH + rowoff + phys, pBh + j * 8);
    }
}

// ---------------- GEMM + fused LSTM epilogue ----------------
__global__ __launch_bounds__(256, 2) void lstm_gemm_kernel(
    const float* __restrict__ c_prev,
    const float* __restrict__ bfp, const float* __restrict__ bip,
    const float* __restrict__ bgp, const float* __restrict__ bop,
    float* __restrict__ h_out, float* __restrict__ c_out)
{
    extern __shared__ char smem[];
    unsigned sb = smem_u32(smem);
    const int t = threadIdx.x;
    const int w = t >> 5, lane = t & 31;
    const int m0  = blockIdx.y * BM;
    const int np0 = blockIdx.x * BNP;

    const int wm = (w >> 2) * 64;
    const int wn = (w & 3) * 32;

    // A ldmatrix lane mapping (64B rows)
    const int lr = lane & 15;
    const int lc = lane >> 4;
    const unsigned swA = (unsigned)((lr >> 1) & 3);
    // B ldmatrix x4-pair lane mapping
    const int lb    = lane & 7;
    const int mid   = lane >> 3;
    const int niSel = mid >> 1;
    const int msub  = mid & 1;
    const unsigned swB = (unsigned)((lb >> 1) & 3);

    unsigned aRow[4], bRowP[2];
    #pragma unroll
    for (int mi = 0; mi < 4; mi++) aRow[mi] = (unsigned)(wm + mi * 16 + lr) * 64;
    #pragma unroll
    for (int p = 0; p < 2; p++) bRowP[p] = (unsigned)(wn + (p * 2 + niSel) * 8 + lb) * 64;

    // accumulators initialized with biases (col-mapped)
    const int tg = lane & 3;
    float acc[4][4][4];
    #pragma unroll
    for (int ni = 0; ni < 4; ni++) {
        int col0 = np0 + wn + ni * 8 + tg * 2;
        float b0, b1;
        {
            int g = col0 & 3, n = col0 >> 2;
            const float* p = (g == 0) ? bfp : (g == 1) ? bip : (g == 2) ? bgp : bop;
            b0 = p[n];
        }
        {
            int c1 = col0 + 1;
            int g = c1 & 3, n = c1 >> 2;
            const float* p = (g == 0) ? bfp : (g == 1) ? bip : (g == 2) ? bgp : bop;
            b1 = p[n];
        }
        #pragma unroll
        for (int mi = 0; mi < 4; mi++) {
            acc[mi][ni][0] = b0; acc[mi][ni][1] = b1;
            acc[mi][ni][2] = b0; acc[mi][ni][3] = b1;
        }
    }

    // prologue: 5 stages in flight (slots 0..4)
    #pragma unroll
    for (int p = 0; p < 5; p++) {
        load_stage(sb + (unsigned)p * STAGE_BYTES, p, m0, np0, t);
        CPA_COMMIT();
    }

    unsigned rdIdx = 0;   // slot of stage s0
    unsigned wrIdx = 5;   // slot for next prefetched stage
    for (int p = 0; p < PAIRS; p++) {
        const int s0 = 2 * p;
        if (p < PAIRS - 2) CPA_WAIT3(); else CPA_WAIT0();
        __syncthreads();
        // prefetch two future stages into the two free slots
        if (s0 + 5 < KSTAGES) {
            load_stage(sb + wrIdx * STAGE_BYTES, s0 + 5, m0, np0, t);
            CPA_COMMIT();
            if (++wrIdx == NBUF) wrIdx = 0;
        }
        if (s0 + 6 < KSTAGES) {
            load_stage(sb + wrIdx * STAGE_BYTES, s0 + 6, m0, np0, t);
            CPA_COMMIT();
            if (++wrIdx == NBUF) wrIdx = 0;
        }

        // barrier-free window: stages s0 and s0+1 both resident
        #pragma unroll
        for (int half = 0; half < 2; half++) {
            unsigned base = sb + rdIdx * STAGE_BYTES;
            if (++rdIdx == NBUF) rdIdx = 0;
            #pragma unroll
            for (int k16 = 0; k16 < 2; k16++) {
                const unsigned cA = ((unsigned)(k16 * 2 + lc)   ^ swA) * 16;
                const unsigned cB = ((unsigned)(k16 * 2 + msub) ^ swB) * 16;

                unsigned bh[4][2];
                ldsm4(bh[0][0], bh[0][1], bh[1][0], bh[1][1], base + OFF_BH + bRowP[0] + cB);
                ldsm4(bh[2][0], bh[2][1], bh[3][0], bh[3][1], base + OFF_BH + bRowP[1] + cB);

                #pragma unroll
                for (int mi = 0; mi < 4; mi++) {
                    unsigned ah[4];
                    ldsm4(ah[0], ah[1], ah[2], ah[3], base + OFF_AH + aRow[mi] + cA);
                    #pragma unroll
                    for (int ni = 0; ni < 4; ni++)
                        mma16816(acc[mi][ni], ah, bh[ni]);
                }
            }
        }
    }

    // ---- fused LSTM epilogue (biases already in acc, fast-math MUFU) ----
    const int g8   = lane >> 2;
    const int odd  = tg & 1;
    const int nsel = tg >> 1;
    const int nwbase = blockIdx.x * 32 + (w & 3) * 8;

    #pragma unroll
    for (int mi = 0; mi < 4; mi++) {
        const int rbase = m0 + wm + mi * 16 + g8;
        const int row = rbase + (odd ? 8 : 0);
        #pragma unroll
        for (int ni = 0; ni < 4; ni++) {
            const int nout = nwbase + ni * 2 + nsel;
            float c0 = acc[mi][ni][0], c1 = acc[mi][ni][1];
            float c2 = acc[mi][ni][2], c3 = acc[mi][ni][3];
            float v0 = __shfl_xor_sync(0xffffffffu, c0, 1);
            float v1 = __shfl_xor_sync(0xffffffffu, c1, 1);
            float v2 = __shfl_xor_sync(0xffffffffu, c2, 1);
            float v3 = __shfl_xor_sync(0xffffffffu, c3, 1);
            float F = odd ? v2 : c0;
            float I = odd ? v3 : c1;
            float G = odd ? c2 : v0;
            float O = odd ? c3 : v1;

            size_t idx = (size_t)row * H_DIM + nout;
            float cp = c_prev[idx];
            float fg = fsigmoid(F);
            float ig = fsigmoid(I);
            float gg = ftanh(G);
            float og = fsigmoid(O);
            float cn = fg * cp + ig * gg;
            c_out[idx] = cn;
            h_out[idx] = og * ftanh(cn);
        }
    }
}

// ---------------- launch ----------------
extern "C" void kernel_launch(void* const* d_in, const int* in_sizes, int n_in,
                              void* d_out, int out_size) {
    const float* x      = (const float*)d_in[0];
    const float* h_prev = (const float*)d_in[1];
    const float* c_prev = (const float*)d_in[2];
    const float* Wf     = (const float*)d_in[3];
    const float* bf     = (const float*)d_in[4];
    const float* Wi     = (const float*)d_in[5];
    const float* bi     = (const float*)d_in[6];
    const float* Wg     = (const float*)d_in[7];
    const float* bg     = (const float*)d_in[8];
    const float* Wo     = (const float*)d_in[9];
    const float* bo     = (const float*)d_in[10];

    float* out   = (float*)d_out;
    float* h_out = out;
    float* c_out = out + (size_t)B_DIM * H_DIM;

    cudaFuncSetAttribute(lstm_gemm_kernel,
                         cudaFuncAttributeMaxDynamicSharedMemorySize, SMEM_TOTAL);

    conv_kernel<<<B_DIM + 2048, 256>>>(x, h_prev, Wf, Wi, Wg, Wo);
    lstm_gemm_kernel<<<dim3(4 * H_DIM / BNP, B_DIM / BM), 256, SMEM_TOTAL>>>(
        c_prev, bf, bi, bg, bo, h_out, c_out);
}

// round 12
// speedup vs baseline: 1.5159x; 1.0108x over previous
#include <cuda_runtime.h>
#include <cuda_fp16.h>
#include <math.h>

#define B_DIM 4096
#define H_DIM 1024
#define K_DIM 2048

// GEMM tiling: C[4096 m][4096 n'] where n' = n*4 + gate (gate-interleaved)
// CTA: 256 threads = 8 warps (2m x 4n), warp tile 64m x 32n'
// Persistent: grid = 304 CTAs (2/SM x 152 SMs); each CTA loops tiles
// bid, bid+304, ... with ONE continuous cp.async stream across tiles
// (loader cursor 5 stages ahead; uniform WAIT3 cadence; no per-tile drain).
#define BM 128
#define BNP 128
#define BK 32                 // k per stage
#define KSTAGES (K_DIM / BK)  // 64
#define PAIRS (KSTAGES / 2)   // 32
#define NBUF 7
#define NTILES 1024           // 32 x 32
#define GRID_P 304

// ---------------- device scratch (allocation-free rule: __device__ globals) ----
__device__ __align__(1024) __half g_Ah[(size_t)B_DIM * K_DIM];
__device__ __align__(1024) __half g_Bh[(size_t)4 * H_DIM * K_DIM];

// ---------------- helpers ----------------
__device__ __forceinline__ unsigned smem_u32(const void* p) {
    unsigned a;
    asm("{ .reg .u64 t; cvta.to.shared.u64 t, %1; cvt.u32.u64 %0, t; }" : "=r"(a) : "l"(p));
    return a;
}
__device__ __forceinline__ void cpa16(unsigned dst, const void* src) {
    asm volatile("cp.async.cg.shared.global [%0], [%1], 16;" :: "r"(dst), "l"(src) : "memory");
}
#define CPA_COMMIT() asm volatile("cp.async.commit_group;" ::: "memory")
#define CPA_WAIT3()  asm volatile("cp.async.wait_group 3;" ::: "memory")
#define CPA_WAIT0()  asm volatile("cp.async.wait_group 0;" ::: "memory")

__device__ __forceinline__ void ldsm4(unsigned &r0, unsigned &r1, unsigned &r2, unsigned &r3,
                                      unsigned addr) {
    asm volatile("ldmatrix.sync.aligned.m8n8.x4.shared.b16 {%0,%1,%2,%3}, [%4];"
                 : "=r"(r0), "=r"(r1), "=r"(r2), "=r"(r3) : "r"(addr));
}
__device__ __forceinline__ void mma16816(float* c, const unsigned* a, const unsigned* b) {
    asm volatile(
        "mma.sync.aligned.m16n8k16.row.col.f32.f16.f16.f32 "
        "{%0,%1,%2,%3}, {%4,%5,%6,%7}, {%8,%9}, {%0,%1,%2,%3};"
        : "+f"(c[0]), "+f"(c[1]), "+f"(c[2]), "+f"(c[3])
        : "r"(a[0]), "r"(a[1]), "r"(a[2]), "r"(a[3]), "r"(b[0]), "r"(b[1]));
}

__device__ __forceinline__ float fsigmoid(float x) {
    return 1.0f / (1.0f + __expf(-x));
}
__device__ __forceinline__ float ftanh(float x) {
    return 2.0f / (1.0f + __expf(-2.0f * x)) - 1.0f;
}

// ---------------- merged conversion kernel ----------------
__global__ __launch_bounds__(256) void conv_kernel(
    const float* __restrict__ x, const float* __restrict__ h_prev,
    const float* __restrict__ Wf, const float* __restrict__ Wi,
    const float* __restrict__ Wg, const float* __restrict__ Wo)
{
    __shared__ float s[64][65];
    int bid = blockIdx.x, t = threadIdx.x;
    if (bid < B_DIM) {
        int k = t * 8;
        const float* src = (k < H_DIM) ? (x + (size_t)bid * H_DIM + k)
                                       : (h_prev + (size_t)bid * H_DIM + (k - H_DIM));
        float4 v0 = *reinterpret_cast<const float4*>(src);
        float4 v1 = *reinterpret_cast<const float4*>(src + 4);
        float vs[8] = {v0.x, v0.y, v0.z, v0.w, v1.x, v1.y, v1.z, v1.w};
        __align__(16) __half hi[8];
        #pragma unroll
        for (int j = 0; j < 8; j++) hi[j] = __float2half_rn(vs[j]);
        *reinterpret_cast<uint4*>(g_Ah + (size_t)bid * K_DIM + k) = *reinterpret_cast<uint4*>(hi);
    } else {
        int w = bid - B_DIM;
        int k0 = (w & 31) * 64;
        int n0 = ((w >> 5) & 15) * 64;
        int g  = w >> 9;
        const float* W = (g == 0) ? Wf : (g == 1) ? Wi : (g == 2) ? Wg : Wo;
        #pragma unroll
        for (int i = 0; i < 4; i++) {
            int idx4 = t + i * 256;
            int kr = idx4 >> 4;
            int c4 = idx4 & 15;
            float4 v = *reinterpret_cast<const float4*>(
                &W[(size_t)(k0 + kr) * H_DIM + n0 + c4 * 4]);
            s[kr][c4 * 4 + 0] = v.x;
            s[kr][c4 * 4 + 1] = v.y;
            s[kr][c4 * 4 + 2] = v.z;
            s[kr][c4 * 4 + 3] = v.w;
        }
        __syncthreads();
        #pragma unroll
        for (int i = 0; i < 8; i++) {
            int idx2 = t + i * 256;
            int nn = idx2 >> 5;
            int kp = idx2 & 31;
            __half2 hv = __floats2half2_rn(s[kp * 2][nn], s[kp * 2 + 1][nn]);
            *reinterpret_cast<__half2*>(
                &g_Bh[(size_t)((n0 + nn) * 4 + g) * K_DIM + k0 + kp * 2]) = hv;
        }
    }
}

// ---------------- smem stage layout ----------------
#define OFF_AH 0
#define OFF_BH (8 * 1024)
#define STAGE_BYTES (16 * 1024)
#define SMEM_TOTAL (NBUF * STAGE_BYTES)   // 112 KB -> 2 CTAs/SM

__device__ __forceinline__ void load_stage(unsigned base, int s, int m0, int np0, int t) {
    int r = t >> 1;
    int cpair = (t & 1) * 2;
    unsigned rowoff = (unsigned)r * 64;
    unsigned sw = (unsigned)((r >> 1) & 3);
    const __half* pAh = g_Ah + (size_t)(m0 + r) * K_DIM + s * BK + cpair * 8;
    const __half* pBh = g_Bh + (size_t)(np0 + r) * K_DIM + s * BK + cpair * 8;
    #pragma unroll
    for (int j = 0; j < 2; j++) {
        unsigned phys = ((unsigned)(cpair + j) ^ sw) * 16;
        cpa16(base + OFF_AH + rowoff + phys, pAh + j * 8);
        cpa16(base + OFF_BH + rowoff + phys, pBh + j * 8);
    }
}

// ---------------- persistent GEMM + fused LSTM epilogue ----------------
__global__ __launch_bounds__(256, 2) void lstm_gemm_kernel(
    const float* __restrict__ c_prev,
    const float* __restrict__ bfp, const float* __restrict__ bip,
    const float* __restrict__ bgp, const float* __restrict__ bop,
    float* __restrict__ h_out, float* __restrict__ c_out)
{
    extern __shared__ char smem[];
    unsigned sb = smem_u32(smem);
    const int t = threadIdx.x;
    const int w = t >> 5, lane = t & 31;
    const int bid = blockIdx.x;

    const int wm = (w >> 2) * 64;
    const int wn = (w & 3) * 32;

    const int lr = lane & 15;
    const int lc = lane >> 4;
    const unsigned swA = (unsigned)((lr >> 1) & 3);
    const int lb    = lane & 7;
    const int mid   = lane >> 3;
    const int niSel = mid >> 1;
    const int msub  = mid & 1;
    const unsigned swB = (unsigned)((lb >> 1) & 3);

    unsigned aRow[4], bRowP[2];
    #pragma unroll
    for (int mi = 0; mi < 4; mi++) aRow[mi] = (unsigned)(wm + mi * 16 + lr) * 64;
    #pragma unroll
    for (int p = 0; p < 2; p++) bRowP[p] = (unsigned)(wn + (p * 2 + niSel) * 8 + lb) * 64;

    const int tg   = lane & 3;
    const int g8   = lane >> 2;
    const int odd  = tg & 1;
    const int nsel = tg >> 1;

    // ---- continuous loader cursor (5 stages ahead, crosses tile boundaries) ----
    int lTile = bid;          // tile being loaded
    int lS = 0;               // next stage within lTile
    unsigned wrIdx = 0, rdIdx = 0;

    #define ISSUE_LOAD() do { \
        if (lTile < NTILES) { \
            int _m0  = (lTile >> 5) * BM; \
            int _np0 = (lTile & 31) * BNP; \
            load_stage(sb + wrIdx * STAGE_BYTES, lS, _m0, _np0, t); \
            CPA_COMMIT(); \
            if (++wrIdx == NBUF) wrIdx = 0; \
            if (++lS == KSTAGES) { lS = 0; lTile += GRID_P; } \
        } \
    } while (0)

    if (bid < NTILES) {
        #pragma unroll
        for (int p = 0; p < 5; p++) ISSUE_LOAD();
    }

    float acc[4][4][4];

    for (int tile = bid; tile < NTILES; tile += GRID_P) {
        const int m0  = (tile >> 5) * BM;
        const int np0 = (tile & 31) * BNP;

        // accumulators initialized with biases (col-mapped)
        #pragma unroll
        for (int ni = 0; ni < 4; ni++) {
            int col0 = np0 + wn + ni * 8 + tg * 2;
            float b0, b1;
            {
                int g = col0 & 3, n = col0 >> 2;
                const float* p = (g == 0) ? bfp : (g == 1) ? bip : (g == 2) ? bgp : bop;
                b0 = p[n];
            }
            {
                int c1 = col0 + 1;
                int g = c1 & 3, n = c1 >> 2;
                const float* p = (g == 0) ? bfp : (g == 1) ? bip : (g == 2) ? bgp : bop;
                b1 = p[n];
            }
            #pragma unroll
            for (int mi = 0; mi < 4; mi++) {
                acc[mi][ni][0] = b0; acc[mi][ni][1] = b1;
                acc[mi][ni][2] = b0; acc[mi][ni][3] = b1;
            }
        }

        for (int p = 0; p < PAIRS; p++) {
            if (lTile < NTILES) CPA_WAIT3(); else CPA_WAIT0();
            __syncthreads();
            ISSUE_LOAD();
            ISSUE_LOAD();

            #pragma unroll
            for (int half = 0; half < 2; half++) {
                unsigned base = sb + rdIdx * STAGE_BYTES;
                if (++rdIdx == NBUF) rdIdx = 0;
                #pragma unroll
                for (int k16 = 0; k16 < 2; k16++) {
                    const unsigned cA = ((unsigned)(k16 * 2 + lc)   ^ swA) * 16;
                    const unsigned cB = ((unsigned)(k16 * 2 + msub) ^ swB) * 16;

                    unsigned bh[4][2];
                    ldsm4(bh[0][0], bh[0][1], bh[1][0], bh[1][1], base + OFF_BH + bRowP[0] + cB);
                    ldsm4(bh[2][0], bh[2][1], bh[3][0], bh[3][1], base + OFF_BH + bRowP[1] + cB);

                    #pragma unroll
                    for (int mi = 0; mi < 4; mi++) {
                        unsigned ah[4];
                        ldsm4(ah[0], ah[1], ah[2], ah[3], base + OFF_AH + aRow[mi] + cA);
                        #pragma unroll
                        for (int ni = 0; ni < 4; ni++)
                            mma16816(acc[mi][ni], ah, bh[ni]);
                    }
                }
            }
        }

        // ---- fused LSTM epilogue (overlaps next tile's in-flight loads) ----
        const int nwbase = (np0 >> 2) + (w & 3) * 8;
        #pragma unroll
        for (int mi = 0; mi < 4; mi++) {
            const int rbase = m0 + wm + mi * 16 + g8;
            const int row = rbase + (odd ? 8 : 0);
            #pragma unroll
            for (int ni = 0; ni < 4; ni++) {
                const int nout = nwbase + ni * 2 + nsel;
                float c0 = acc[mi][ni][0], c1 = acc[mi][ni][1];
                float c2 = acc[mi][ni][2], c3 = acc[mi][ni][3];
                float v0 = __shfl_xor_sync(0xffffffffu, c0, 1);
                float v1 = __shfl_xor_sync(0xffffffffu, c1, 1);
                float v2 = __shfl_xor_sync(0xffffffffu, c2, 1);
                float v3 = __shfl_xor_sync(0xffffffffu, c3, 1);
                float F = odd ? v2 : c0;
                float I = odd ? v3 : c1;
                float G = odd ? c2 : v0;
                float O = odd ? c3 : v1;

                size_t idx = (size_t)row * H_DIM + nout;
                float cp = c_prev[idx];
                float fg = fsigmoid(F);
                float ig = fsigmoid(I);
                float gg = ftanh(G);
                float og = fsigmoid(O);
                float cn = fg * cp + ig * gg;
                c_out[idx] = cn;
                h_out[idx] = og * ftanh(cn);
            }
        }
    }
}

// ---------------- launch ----------------
extern "C" void kernel_launch(void* const* d_in, const int* in_sizes, int n_in,
                              void* d_out, int out_size) {
    const float* x      = (const float*)d_in[0];
    const float* h_prev = (const float*)d_in[1];
    const float* c_prev = (const float*)d_in[2];
    const float* Wf     = (const float*)d_in[3];
    const float* bf     = (const float*)d_in[4];
    const float* Wi     = (const float*)d_in[5];
    const float* bi     = (const float*)d_in[6];
    const float* Wg     = (const float*)d_in[7];
    const float* bg     = (const float*)d_in[8];
    const float* Wo     = (const float*)d_in[9];
    const float* bo     = (const float*)d_in[10];

    float* out   = (float*)d_out;
    float* h_out = out;
    float* c_out = out + (size_t)B_DIM * H_DIM;

    cudaFuncSetAttribute(lstm_gemm_kernel,
                         cudaFuncAttributeMaxDynamicSharedMemorySize, SMEM_TOTAL);

    conv_kernel<<<B_DIM + 2048, 256>>>(x, h_prev, Wf, Wi, Wg, Wo);
    lstm_gemm_kernel<<<GRID_P, 256, SMEM_TOTAL>>>(
        c_prev, bf, bi, bg, bo, h_out, c_out);
}